// round 3
// baseline (speedup 1.0000x reference)
#include <cuda_runtime.h>
#include <math.h>

// Problem constants (B=2, T=16, N=1024, D=3)
#define BT        32
#define NPTS      1024
#define TPB       128
#define POWN      8                   // owned points per thread per direction
#define NCHUNK    8                   // candidate chunks per batch
#define CCHUNK    (NPTS / NCHUNK)     // 128 candidates per chunk per direction
#define CPAIRS    (CCHUNK / 2)        // 64 packed candidate pairs
#define NBLOCKS   (BT * NCHUNK)       // 256
#define EPS       1e-6f

// Global scratch (zero-initialized at module load; kernel restores zeros each
// launch so CUDA-graph replays see a clean state).
__device__ unsigned int g_m1[BT * NPTS];   // enc(max_i (x_j . y_i - 0.5||y_i||^2))
__device__ unsigned int g_m2[BT * NPTS];   // enc(max_j (y_i . x_j - 0.5||x_j||^2))
__device__ unsigned int g_bcount[BT];
__device__ float        g_bsum[BT];
__device__ unsigned int g_fcount;

// ---- packed f32x2 helpers (sm_100+; ptxas never auto-fuses) ----
__device__ __forceinline__ unsigned long long pack2(float a, float b) {
    unsigned long long r;
    asm("mov.b64 %0, {%1, %2};" : "=l"(r) : "f"(a), "f"(b));
    return r;
}
__device__ __forceinline__ unsigned long long fma2(unsigned long long a,
                                                   unsigned long long b,
                                                   unsigned long long c) {
    unsigned long long d;
    asm("fma.rn.f32x2 %0, %1, %2, %3;" : "=l"(d) : "l"(a), "l"(b), "l"(c));
    return d;
}
__device__ __forceinline__ void unpack2(unsigned long long v, float& lo, float& hi) {
    asm("mov.b64 {%0, %1}, %2;" : "=f"(lo), "=f"(hi) : "l"(v));
}

// Monotone float<->uint encoding: enc preserves order under unsigned compare.
// All finite floats encode to >= 0x00800000, so a zeroed word acts as -inf.
__device__ __forceinline__ unsigned int enc_f(float f) {
    unsigned int u = __float_as_uint(f);
    return (u & 0x80000000u) ? ~u : (u | 0x80000000u);
}
__device__ __forceinline__ float dec_f(unsigned int u) {
    unsigned int v = (u & 0x80000000u) ? (u ^ 0x80000000u) : ~u;
    return __uint_as_float(v);
}

__global__ void __launch_bounds__(TPB, 2)
chamfer_kernel(const float* __restrict__ x, const float* __restrict__ y,
               float* __restrict__ out) {
    // Candidate stage: per pair of points, 32B = {x0,x1, y0,y1, z0,z1, -h0,-h1}
    __shared__ float s_y[CPAIRS * 8];
    __shared__ float s_x[CPAIRS * 8];
    __shared__ float warp_sums[TPB / 32];
    __shared__ bool  sh_last, sh_fin;

    const int bt    = blockIdx.x >> 3;      // batch
    const int chunk = blockIdx.x & 7;       // candidate chunk
    const int tid   = threadIdx.x;
    const float* xb = x + (size_t)bt * NPTS * 3;
    const float* yb = y + (size_t)bt * NPTS * 3;

    // ---- stage this chunk's candidates (128 y + 128 x) into packed pairs ----
    {
        const int p  = tid;                 // local candidate index 0..127
        const int gp = chunk * CCHUNK + p;  // global candidate index
        const int pr = p >> 1, s = p & 1, base = 8 * pr + s;

        float b0 = yb[3 * gp + 0], b1 = yb[3 * gp + 1], b2 = yb[3 * gp + 2];
        s_y[base + 0] = b0;
        s_y[base + 2] = b1;
        s_y[base + 4] = b2;
        s_y[base + 6] = -0.5f * (b0 * b0 + b1 * b1 + b2 * b2);

        float a0 = xb[3 * gp + 0], a1 = xb[3 * gp + 1], a2 = xb[3 * gp + 2];
        s_x[base + 0] = a0;
        s_x[base + 2] = a1;
        s_x[base + 4] = a2;
        s_x[base + 6] = -0.5f * (a0 * a0 + a1 * a1 + a2 * a2);
    }

    // ---- load owned register tiles: 8 x-points + 8 y-points (splatted) ----
    unsigned long long Xx2[POWN], Xy2[POWN], Xz2[POWN];
    unsigned long long Yx2[POWN], Yy2[POWN], Yz2[POWN];
    float hX[POWN], hY[POWN];
#pragma unroll
    for (int k = 0; k < POWN; ++k) {
        const int pid = tid + TPB * k;      // owned point index in batch
        float a0 = xb[3 * pid + 0], a1 = xb[3 * pid + 1], a2 = xb[3 * pid + 2];
        Xx2[k] = pack2(a0, a0);
        Xy2[k] = pack2(a1, a1);
        Xz2[k] = pack2(a2, a2);
        hX[k]  = 0.5f * (a0 * a0 + a1 * a1 + a2 * a2);

        float b0 = yb[3 * pid + 0], b1 = yb[3 * pid + 1], b2 = yb[3 * pid + 2];
        Yx2[k] = pack2(b0, b0);
        Yy2[k] = pack2(b1, b1);
        Yz2[k] = pack2(b2, b2);
        hY[k]  = 0.5f * (b0 * b0 + b1 * b1 + b2 * b2);
    }
    __syncthreads();

    float m1lo[POWN], m1hi[POWN], m2lo[POWN], m2hi[POWN];
#pragma unroll
    for (int k = 0; k < POWN; ++k) {
        m1lo[k] = -INFINITY; m1hi[k] = -INFINITY;
        m2lo[k] = -INFINITY; m2hi[k] = -INFINITY;
    }

    // ---- hot loops: one candidate-pair load feeds 8 owned points ----
    const ulonglong2* syp = (const ulonglong2*)s_y;
    const ulonglong2* sxp = (const ulonglong2*)s_x;

#pragma unroll 4
    for (int pr = 0; pr < CPAIRS; ++pr) {
        ulonglong2 va = syp[2 * pr];        // (x0,x1),(y0,y1)
        ulonglong2 vb = syp[2 * pr + 1];    // (z0,z1),(-h0,-h1)
#pragma unroll
        for (int k = 0; k < POWN; ++k) {
            unsigned long long t = fma2(Xz2[k], vb.x, vb.y);
            t = fma2(Xy2[k], va.y, t);
            t = fma2(Xx2[k], va.x, t);
            float lo, hi;
            unpack2(t, lo, hi);
            m1lo[k] = fmaxf(m1lo[k], lo);
            m1hi[k] = fmaxf(m1hi[k], hi);
        }
    }

#pragma unroll 4
    for (int pr = 0; pr < CPAIRS; ++pr) {
        ulonglong2 va = sxp[2 * pr];
        ulonglong2 vb = sxp[2 * pr + 1];
#pragma unroll
        for (int k = 0; k < POWN; ++k) {
            unsigned long long t = fma2(Yz2[k], vb.x, vb.y);
            t = fma2(Yy2[k], va.y, t);
            t = fma2(Yx2[k], va.x, t);
            float lo, hi;
            unpack2(t, lo, hi);
            m2lo[k] = fmaxf(m2lo[k], lo);
            m2hi[k] = fmaxf(m2hi[k], hi);
        }
    }

    // ---- publish partial maxes (order-independent: exact fp max) ----
#pragma unroll
    for (int k = 0; k < POWN; ++k) {
        const int idx = bt * NPTS + tid + TPB * k;
        atomicMax(&g_m1[idx], enc_f(fmaxf(m1lo[k], m1hi[k])));
        atomicMax(&g_m2[idx], enc_f(fmaxf(m2lo[k], m2hi[k])));
    }
    __threadfence();

    if (tid == 0) {
        unsigned int done = atomicAdd(&g_bcount[bt], 1u);
        sh_last = (done == NCHUNK - 1);
    }
    __syncthreads();
    if (!sh_last) return;

    // ---- last chunk of this batch combines: it owns ALL the batch's points,
    //      so the h-norms are already in registers ----
    float sum = 0.0f;
#pragma unroll
    for (int k = 0; k < POWN; ++k) {
        const int idx = bt * NPTS + tid + TPB * k;
        float m1 = dec_f(__ldcg(&g_m1[idx]));
        float m2 = dec_f(__ldcg(&g_m2[idx]));
        g_m1[idx] = 0u;                     // restore -inf for next replay
        g_m2[idx] = 0u;
        float sq1 = fmaxf(2.0f * (hX[k] - m1), 0.0f);
        float sq2 = fmaxf(2.0f * (hY[k] - m2), 0.0f);
        sum += sqrtf(EPS + sq1) + sqrtf(EPS + sq2);
    }

    // block reduction over 128 threads
#pragma unroll
    for (int off = 16; off > 0; off >>= 1)
        sum += __shfl_down_sync(0xFFFFFFFFu, sum, off);
    if ((tid & 31) == 0) warp_sums[tid >> 5] = sum;
    __syncthreads();

    if (tid == 0) {
        float s = 0.0f;
#pragma unroll
        for (int w = 0; w < TPB / 32; ++w) s += warp_sums[w];
        g_bsum[bt]   = s;
        g_bcount[bt] = 0u;                  // reset batch counter for replay
        __threadfence();
        unsigned int done = atomicAdd(&g_fcount, 1u);
        sh_fin = (done == BT - 1);
    }
    __syncthreads();
    if (!sh_fin) return;

    // ---- final: one thread sums 32 batch sums in fixed order ----
    if (tid == 0) {
        float s = 0.0f;
#pragma unroll
        for (int b = 0; b < BT; ++b) s += __ldcg(&g_bsum[b]);
        out[0]   = s * (1.0f / (float)(BT * NPTS));
        g_fcount = 0u;                      // reset for next replay
    }
}

extern "C" void kernel_launch(void* const* d_in, const int* in_sizes, int n_in,
                              void* d_out, int out_size) {
    const float* x = (const float*)d_in[0];
    const float* y = (const float*)d_in[1];
    float* out = (float*)d_out;
    (void)in_sizes; (void)n_in; (void)out_size;

    chamfer_kernel<<<NBLOCKS, TPB>>>(x, y, out);
}

// round 4
// speedup vs baseline: 1.3249x; 1.3249x over previous
#include <cuda_runtime.h>
#include <math.h>

// Problem constants (B=2, T=16, N=1024, D=3)
#define BT       32
#define NPTS     1024
#define TPB      256
#define OCH      8                    // owned-point chunks per (batch, direction)
#define OWNED    (NPTS / OCH)         // 128 owned points per block
#define POWN     2                    // owned points per thread
#define NQ       4                    // candidate quarters (lane&3)
#define CPAIRS   (NPTS / 2)           // 512 packed candidate pairs in smem
#define ITERS    (CPAIRS / NQ)        // 128 pair-iterations per thread
#define NBLOCKS  (BT * 2 * OCH)       // 512
#define EPS      1e-6f

__device__ float        g_partials[NBLOCKS];
__device__ unsigned int g_count = 0;

// ---- packed f32x2 helpers (sm_100+; ptxas never auto-fuses) ----
__device__ __forceinline__ unsigned long long pack2(float a, float b) {
    unsigned long long r;
    asm("mov.b64 %0, {%1, %2};" : "=l"(r) : "f"(a), "f"(b));
    return r;
}
__device__ __forceinline__ unsigned long long fma2(unsigned long long a,
                                                   unsigned long long b,
                                                   unsigned long long c) {
    unsigned long long d;
    asm("fma.rn.f32x2 %0, %1, %2, %3;" : "=l"(d) : "l"(a), "l"(b), "l"(c));
    return d;
}
__device__ __forceinline__ void unpack2(unsigned long long v, float& lo, float& hi) {
    asm("mov.b64 {%0, %1}, %2;" : "=f"(lo), "=f"(hi) : "l"(v));
}

__global__ void __launch_bounds__(TPB, 2)
chamfer_kernel(const float* __restrict__ x, const float* __restrict__ y,
               float* __restrict__ out) {
    // Candidate pairs: 32B each = {x0,x1, y0,y1, z0,z1, -h0,-h1}; 512 pairs = 16KB
    __shared__ float s_c[CPAIRS * 8];
    __shared__ float warp_sums[TPB / 32];
    __shared__ bool  sh_last;

    const int bt    = blockIdx.x >> 4;          // batch
    const int dir   = (blockIdx.x >> 3) & 1;    // 0: owned=x, cand=y; 1: reverse
    const int chunk = blockIdx.x & 7;           // owned chunk
    const int tid   = threadIdx.x;

    const float* xb = x + (size_t)bt * NPTS * 3;
    const float* yb = y + (size_t)bt * NPTS * 3;
    const float* ownp = dir ? yb : xb;
    const float* cndp = dir ? xb : yb;

    // ---- stage ALL 1024 candidates of this direction, packed in pairs ----
    for (int p = tid; p < NPTS; p += TPB) {
        const int base = 8 * (p >> 1) + (p & 1);
        float c0 = cndp[3 * p + 0], c1 = cndp[3 * p + 1], c2 = cndp[3 * p + 2];
        s_c[base + 0] = c0;
        s_c[base + 2] = c1;
        s_c[base + 4] = c2;
        s_c[base + 6] = -0.5f * (c0 * c0 + c1 * c1 + c2 * c2);
    }

    // ---- owned register tile: 2 points, splatted for f32x2 ----
    const int q  = tid & 3;                     // candidate quarter
    const int oi = tid >> 2;                    // 0..63
    unsigned long long Ax2[POWN], Ay2[POWN], Az2[POWN];
    float h[POWN];
#pragma unroll
    for (int k = 0; k < POWN; ++k) {
        const int o = chunk * OWNED + oi + 64 * k;
        float a0 = ownp[3 * o + 0], a1 = ownp[3 * o + 1], a2 = ownp[3 * o + 2];
        Ax2[k] = pack2(a0, a0);
        Ay2[k] = pack2(a1, a1);
        Az2[k] = pack2(a2, a2);
        h[k]   = 0.5f * (a0 * a0 + a1 * a1 + a2 * a2);
    }
    __syncthreads();

    float mlo[POWN], mhi[POWN];
#pragma unroll
    for (int k = 0; k < POWN; ++k) { mlo[k] = -INFINITY; mhi[k] = -INFINITY; }

    // ---- hot loop: lane-split candidate pairs (4 distinct pairs per warp-LDS) ----
    const ulonglong2* cp = (const ulonglong2*)s_c;
#pragma unroll 4
    for (int i = 0; i < ITERS; ++i) {
        const int pr = 4 * i + q;
        ulonglong2 va = cp[2 * pr];             // (x0,x1),(y0,y1)
        ulonglong2 vb = cp[2 * pr + 1];         // (z0,z1),(-h0,-h1)
#pragma unroll
        for (int k = 0; k < POWN; ++k) {
            unsigned long long t = fma2(Az2[k], vb.x, vb.y);
            t = fma2(Ay2[k], va.y, t);
            t = fma2(Ax2[k], va.x, t);
            float lo, hi;
            unpack2(t, lo, hi);
            mlo[k] = fmaxf(mlo[k], lo);
            mhi[k] = fmaxf(mhi[k], hi);
        }
    }

    // ---- combine the 4 candidate quarters (adjacent lanes, same warp) ----
    float contrib = 0.0f;
#pragma unroll
    for (int k = 0; k < POWN; ++k) {
        float m = fmaxf(mlo[k], mhi[k]);
        m = fmaxf(m, __shfl_xor_sync(0xFFFFFFFFu, m, 1));
        m = fmaxf(m, __shfl_xor_sync(0xFFFFFFFFu, m, 2));
        // min_i sq = 2*(h - m); clamp, dist = sqrt(EPS + sq)
        float sq = fmaxf(2.0f * (h[k] - m), 0.0f);
        if (q == 0) contrib += sqrtf(EPS + sq);
    }

    // ---- block reduction (fixed order -> deterministic) ----
#pragma unroll
    for (int off = 16; off > 0; off >>= 1)
        contrib += __shfl_down_sync(0xFFFFFFFFu, contrib, off);
    if ((tid & 31) == 0) warp_sums[tid >> 5] = contrib;
    __syncthreads();

    if (tid == 0) {
        float s = 0.0f;
#pragma unroll
        for (int w = 0; w < TPB / 32; ++w) s += warp_sums[w];
        g_partials[blockIdx.x] = s;
        __threadfence();
        unsigned int done = atomicAdd(&g_count, 1u);
        sh_last = (done == NBLOCKS - 1);
    }
    __syncthreads();
    if (!sh_last) return;

    // ---- fused final reduction in the last block (fixed order) ----
    __threadfence();
    float v = __ldcg(&g_partials[tid]) + __ldcg(&g_partials[tid + TPB]);
#pragma unroll
    for (int off = 16; off > 0; off >>= 1)
        v += __shfl_down_sync(0xFFFFFFFFu, v, off);
    if ((tid & 31) == 0) warp_sums[tid >> 5] = v;
    __syncthreads();
    if (tid == 0) {
        float s = 0.0f;
#pragma unroll
        for (int w = 0; w < TPB / 32; ++w) s += warp_sums[w];
        out[0]  = s * (1.0f / (float)(BT * NPTS));
        g_count = 0u;                           // reset for next graph replay
    }
}

extern "C" void kernel_launch(void* const* d_in, const int* in_sizes, int n_in,
                              void* d_out, int out_size) {
    const float* x = (const float*)d_in[0];
    const float* y = (const float*)d_in[1];
    float* out = (float*)d_out;
    (void)in_sizes; (void)n_in; (void)out_size;

    chamfer_kernel<<<NBLOCKS, TPB>>>(x, y, out);
}

// round 5
// speedup vs baseline: 1.6000x; 1.2076x over previous
#include <cuda_runtime.h>
#include <math.h>

// Problem constants (B=2, T=16, N=1024, D=3)
#define BT       32
#define NPTS     1024
#define TPB      256
#define NQ       16                   // candidate lane-split groups
#define POWN     8                    // owned points per thread
#define OWNED    ((TPB / NQ) * POWN)  // 128 owned points per block
#define OCH      (NPTS / OWNED)       // 8 owned chunks per (batch, direction)
#define CPAIRS   (NPTS / 2)           // 512 packed candidate pairs in smem
#define ITERS    (CPAIRS / NQ)        // 32 pair-iterations per thread
#define NBLOCKS  (BT * 2 * OCH)       // 512
#define EPS      1e-6f

__device__ float        g_partials[NBLOCKS];
__device__ unsigned int g_count = 0;

// ---- packed f32x2 helpers (sm_100+; ptxas never auto-fuses) ----
__device__ __forceinline__ unsigned long long pack2(float a, float b) {
    unsigned long long r;
    asm("mov.b64 %0, {%1, %2};" : "=l"(r) : "f"(a), "f"(b));
    return r;
}
__device__ __forceinline__ unsigned long long fma2(unsigned long long a,
                                                   unsigned long long b,
                                                   unsigned long long c) {
    unsigned long long d;
    asm("fma.rn.f32x2 %0, %1, %2, %3;" : "=l"(d) : "l"(a), "l"(b), "l"(c));
    return d;
}
__device__ __forceinline__ void unpack2(unsigned long long v, float& lo, float& hi) {
    asm("mov.b64 {%0, %1}, %2;" : "=f"(lo), "=f"(hi) : "l"(v));
}

__global__ void __launch_bounds__(TPB, 2)
chamfer_kernel(const float* __restrict__ x, const float* __restrict__ y,
               float* __restrict__ out) {
    // Candidate pairs: 32B each = {x0,x1, y0,y1, z0,z1, -h0,-h1}; 512 pairs = 16KB
    __shared__ float s_c[CPAIRS * 8];
    __shared__ float warp_sums[TPB / 32];
    __shared__ bool  sh_last;

    const int bt    = blockIdx.x >> 4;          // batch (32)
    const int dir   = (blockIdx.x >> 3) & 1;    // 0: owned=x, cand=y; 1: reverse
    const int chunk = blockIdx.x & 7;           // owned chunk (8)
    const int tid   = threadIdx.x;

    const float* xb = x + (size_t)bt * NPTS * 3;
    const float* yb = y + (size_t)bt * NPTS * 3;
    const float* ownp = dir ? yb : xb;
    const float* cndp = dir ? xb : yb;

    // ---- stage ALL 1024 candidates of this direction, packed in pairs ----
    for (int p = tid; p < NPTS; p += TPB) {
        const int base = 8 * (p >> 1) + (p & 1);
        float c0 = cndp[3 * p + 0], c1 = cndp[3 * p + 1], c2 = cndp[3 * p + 2];
        s_c[base + 0] = c0;
        s_c[base + 2] = c1;
        s_c[base + 4] = c2;
        s_c[base + 6] = -0.5f * (c0 * c0 + c1 * c1 + c2 * c2);
    }

    // ---- owned register tile: 8 points, splatted for f32x2 ----
    const int q = tid & (NQ - 1);               // candidate group 0..15
    const int g = tid >> 4;                     // owned group 0..15
    unsigned long long Ax2[POWN], Ay2[POWN], Az2[POWN];
    float h[POWN];
#pragma unroll
    for (int k = 0; k < POWN; ++k) {
        const int o = chunk * OWNED + g + (TPB / NQ) * k;
        float a0 = ownp[3 * o + 0], a1 = ownp[3 * o + 1], a2 = ownp[3 * o + 2];
        Ax2[k] = pack2(a0, a0);
        Ay2[k] = pack2(a1, a1);
        Az2[k] = pack2(a2, a2);
        h[k]   = 0.5f * (a0 * a0 + a1 * a1 + a2 * a2);
    }
    __syncthreads();

    float mlo[POWN], mhi[POWN];
#pragma unroll
    for (int k = 0; k < POWN; ++k) { mlo[k] = -INFINITY; mhi[k] = -INFINITY; }

    // ---- hot loop: one candidate-pair load (32B) feeds 8 owned points ----
    const ulonglong2* cp = (const ulonglong2*)s_c;
#pragma unroll 4
    for (int i = 0; i < ITERS; ++i) {
        const int pr = NQ * i + q;
        ulonglong2 va = cp[2 * pr];             // (x0,x1),(y0,y1)
        ulonglong2 vb = cp[2 * pr + 1];         // (z0,z1),(-h0,-h1)
#pragma unroll
        for (int k = 0; k < POWN; ++k) {
            unsigned long long t = fma2(Az2[k], vb.x, vb.y);
            t = fma2(Ay2[k], va.y, t);
            t = fma2(Ax2[k], va.x, t);
            float lo, hi;
            unpack2(t, lo, hi);
            mlo[k] = fmaxf(mlo[k], lo);
            mhi[k] = fmaxf(mhi[k], hi);
        }
    }

    // ---- combine the 16 candidate groups (lanes 0-15 / 16-31 of the warp) ----
    float contrib = 0.0f;
#pragma unroll
    for (int k = 0; k < POWN; ++k) {
        float m = fmaxf(mlo[k], mhi[k]);
        m = fmaxf(m, __shfl_xor_sync(0xFFFFFFFFu, m, 1));
        m = fmaxf(m, __shfl_xor_sync(0xFFFFFFFFu, m, 2));
        m = fmaxf(m, __shfl_xor_sync(0xFFFFFFFFu, m, 4));
        m = fmaxf(m, __shfl_xor_sync(0xFFFFFFFFu, m, 8));
        // min_i sq = 2*(h - m); clamp, dist = sqrt(EPS + sq)
        float sq = fmaxf(2.0f * (h[k] - m), 0.0f);
        if (q == 0) contrib += sqrtf(EPS + sq);
    }

    // ---- block reduction (fixed order -> deterministic) ----
#pragma unroll
    for (int off = 16; off > 0; off >>= 1)
        contrib += __shfl_down_sync(0xFFFFFFFFu, contrib, off);
    if ((tid & 31) == 0) warp_sums[tid >> 5] = contrib;
    __syncthreads();

    if (tid == 0) {
        float s = 0.0f;
#pragma unroll
        for (int w = 0; w < TPB / 32; ++w) s += warp_sums[w];
        g_partials[blockIdx.x] = s;
        __threadfence();
        unsigned int done = atomicAdd(&g_count, 1u);
        sh_last = (done == NBLOCKS - 1);
    }
    __syncthreads();
    if (!sh_last) return;

    // ---- fused final reduction in the last block (fixed order) ----
    __threadfence();
    float v = __ldcg(&g_partials[tid]) + __ldcg(&g_partials[tid + TPB]);
#pragma unroll
    for (int off = 16; off > 0; off >>= 1)
        v += __shfl_down_sync(0xFFFFFFFFu, v, off);
    if ((tid & 31) == 0) warp_sums[tid >> 5] = v;
    __syncthreads();
    if (tid == 0) {
        float s = 0.0f;
#pragma unroll
        for (int w = 0; w < TPB / 32; ++w) s += warp_sums[w];
        out[0]  = s * (1.0f / (float)(BT * NPTS));
        g_count = 0u;                           // reset for next graph replay
    }
}

extern "C" void kernel_launch(void* const* d_in, const int* in_sizes, int n_in,
                              void* d_out, int out_size) {
    const float* x = (const float*)d_in[0];
    const float* y = (const float*)d_in[1];
    float* out = (float*)d_out;
    (void)in_sizes; (void)n_in; (void)out_size;

    chamfer_kernel<<<NBLOCKS, TPB>>>(x, y, out);
}